// round 12
// baseline (speedup 1.0000x reference)
#include <cuda_runtime.h>
#include <cuda_bf16.h>
#include <math.h>
#include <cstdint>

// Problem constants
#define Bsz 4
#define Ssz 4096
#define Hn  8
#define DIc 128
#define DOc 128
#define Tsz (Bsz*Ssz)        // 16384 tokens
#define K1c 256              // 2*DI
#define N1c 384              // 3*DO
#define N2c 128
#define NC  64               // scan chunks
#define LC  (Ssz/NC)         // 64 steps per chunk
#define EPSf 1e-6f

// ---------------- static scratch (device globals; no allocation) -------------
__device__ __align__(16) __nv_bfloat16 buf_xh [(size_t)Tsz*Hn*K1c];  // A1 hi ([in, ln(csum)])
__device__ __align__(16) __nv_bfloat16 buf_xl [(size_t)Tsz*Hn*K1c];  // A1 lo
__device__ __align__(16) __nv_bfloat16 buf_cellh[(size_t)Tsz*Hn*DOc]; // cell hi
__device__ __align__(16) __nv_bfloat16 buf_celll[(size_t)Tsz*Hn*DOc]; // cell lo
__device__ float buf_h3  [(size_t)Tsz*Hn*N1c];
__device__ float buf_og  [(size_t)Tsz*Hn*DOc];
__device__ float buf_chunk[Bsz*NC*Hn*DIc];
__device__ float buf_Fc  [Bsz*NC*Hn*DOc];
__device__ float buf_Ic  [Bsz*NC*Hn*DOc];
__device__ float buf_cst [Bsz*NC*Hn*DOc];
__device__ float2 buf_stats[Tsz];            // (mu, rs) of h3 LN per token
// pre-split / transposed weights: [h][n][k] bf16 hi/lo
__device__ __align__(16) __nv_bfloat16 wt1_hi[(size_t)Hn*N1c*K1c];
__device__ __align__(16) __nv_bfloat16 wt1_lo[(size_t)Hn*N1c*K1c];
__device__ __align__(16) __nv_bfloat16 wt2_hi[(size_t)Hn*N2c*K1c];
__device__ __align__(16) __nv_bfloat16 wt2_lo[(size_t)Hn*N2c*K1c];

// ---------------- PTX helpers -------------------------------------------------
__device__ __forceinline__ uint32_t smem_u32(const void* p) {
    uint32_t a;
    asm("{ .reg .u64 t; cvta.to.shared.u64 t, %1; cvt.u32.u64 %0, t; }" : "=r"(a) : "l"(p));
    return a;
}
#define CPA16(sm_addr, gm_ptr) \
    asm volatile("cp.async.cg.shared.global [%0], [%1], 16;" \
                 :: "r"(sm_addr), "l"(gm_ptr) : "memory")
#define CPA_COMMIT asm volatile("cp.async.commit_group;" ::: "memory")
#define CPA_WAIT0  asm volatile("cp.async.wait_group 0;"  ::: "memory")

#define LDSM_X4(r0,r1,r2,r3,addr) \
    asm volatile("ldmatrix.sync.aligned.m8n8.x4.shared.b16 {%0,%1,%2,%3},[%4];" \
                 : "=r"(r0),"=r"(r1),"=r"(r2),"=r"(r3) : "r"(addr))

#define MMA16816(d, a, b) \
    asm volatile("mma.sync.aligned.m16n8k16.row.col.f32.bf16.bf16.f32 " \
                 "{%0,%1,%2,%3},{%4,%5,%6,%7},{%8,%9},{%0,%1,%2,%3};" \
                 : "+f"((d)[0]),"+f"((d)[1]),"+f"((d)[2]),"+f"((d)[3]) \
                 : "r"((a)[0]),"r"((a)[1]),"r"((a)[2]),"r"((a)[3]), \
                   "r"((b)[0]),"r"((b)[1]))

__device__ __forceinline__ void bsplit(float v, __nv_bfloat16& hi, __nv_bfloat16& lo) {
    hi = __float2bfloat16_rn(v);
    lo = __float2bfloat16_rn(v - __bfloat162float(hi));
}
__device__ __forceinline__ void bsplit4(float4 v, uint2& hi, uint2& lo) {
    __nv_bfloat16 h0,l0,h1,l1,h2,l2,h3,l3;
    bsplit(v.x,h0,l0); bsplit(v.y,h1,l1); bsplit(v.z,h2,l2); bsplit(v.w,h3,l3);
    hi.x = (uint32_t)__bfloat16_as_ushort(h0) | ((uint32_t)__bfloat16_as_ushort(h1) << 16);
    hi.y = (uint32_t)__bfloat16_as_ushort(h2) | ((uint32_t)__bfloat16_as_ushort(h3) << 16);
    lo.x = (uint32_t)__bfloat16_as_ushort(l0) | ((uint32_t)__bfloat16_as_ushort(l1) << 16);
    lo.y = (uint32_t)__bfloat16_as_ushort(l2) | ((uint32_t)__bfloat16_as_ushort(l3) << 16);
}
__device__ __forceinline__ float4 bunpack4(uint2 h, uint2 l) {
    float4 r;
    r.x = __bfloat162float(__ushort_as_bfloat16((unsigned short)(h.x & 0xffff)))
        + __bfloat162float(__ushort_as_bfloat16((unsigned short)(l.x & 0xffff)));
    r.y = __bfloat162float(__ushort_as_bfloat16((unsigned short)(h.x >> 16)))
        + __bfloat162float(__ushort_as_bfloat16((unsigned short)(l.x >> 16)));
    r.z = __bfloat162float(__ushort_as_bfloat16((unsigned short)(h.y & 0xffff)))
        + __bfloat162float(__ushort_as_bfloat16((unsigned short)(l.y & 0xffff)));
    r.w = __bfloat162float(__ushort_as_bfloat16((unsigned short)(h.y >> 16)))
        + __bfloat162float(__ushort_as_bfloat16((unsigned short)(l.y >> 16)));
    return r;
}
__device__ __forceinline__ float4 ld4(const float* p) { return *(const float4*)p; }
__device__ __forceinline__ void st4(float* p, float4 v) { *(float4*)p = v; }

// ---------------- helpers ----------------------------------------------------
// loop-safe (trailing barrier so shared slots can be reused next call)
__device__ __forceinline__ void block_reduce2(float& s, float& ss) {
    __shared__ float shs[32], shss[32];
    #pragma unroll
    for (int o = 16; o > 0; o >>= 1) {
        s  += __shfl_down_sync(0xffffffffu, s,  o);
        ss += __shfl_down_sync(0xffffffffu, ss, o);
    }
    int lane = threadIdx.x & 31, w = threadIdx.x >> 5, nw = blockDim.x >> 5;
    if (lane == 0) { shs[w] = s; shss[w] = ss; }
    __syncthreads();
    if (w == 0) {
        s  = (lane < nw) ? shs[lane]  : 0.f;
        ss = (lane < nw) ? shss[lane] : 0.f;
        #pragma unroll
        for (int o = 16; o > 0; o >>= 1) {
            s  += __shfl_down_sync(0xffffffffu, s,  o);
            ss += __shfl_down_sync(0xffffffffu, ss, o);
        }
        if (lane == 0) { shs[0] = s; shss[0] = ss; }
    }
    __syncthreads();
    s = shs[0]; ss = shss[0];
    __syncthreads();
}

__device__ __forceinline__ float sigm(float x) { return 1.f / (1.f + expf(-x)); }

// ---------------- K0: weight transpose + bf16 split (smem tiled) -------------
template <int WHICH>
__global__ void k_wsplit(const float* __restrict__ W) {
    const int N = (WHICH == 0) ? N1c : N2c;
    __nv_bfloat16* Whi = (WHICH == 0) ? wt1_hi : wt2_hi;
    __nv_bfloat16* Wlo = (WHICH == 0) ? wt1_lo : wt2_lo;
    __shared__ float tile[32][33];
    const int n0 = blockIdx.x * 32, k0 = blockIdx.y * 32, hh = blockIdx.z;
    const int tid = threadIdx.x;
    {
        int r = tid >> 3, cq = tid & 7;
        float4 v = ld4(W + ((size_t)hh * K1c + k0 + r) * N + n0 + cq * 4);
        tile[r][cq * 4 + 0] = v.x; tile[r][cq * 4 + 1] = v.y;
        tile[r][cq * 4 + 2] = v.z; tile[r][cq * 4 + 3] = v.w;
    }
    __syncthreads();
    {
        int nr = tid >> 3, kq = tid & 7;
        float4 v;
        v.x = tile[kq * 4 + 0][nr]; v.y = tile[kq * 4 + 1][nr];
        v.z = tile[kq * 4 + 2][nr]; v.w = tile[kq * 4 + 3][nr];
        uint2 hi, lo;
        bsplit4(v, hi, lo);
        size_t o = ((size_t)hh * N + n0 + nr) * K1c + k0 + kq * 4;
        *(uint2*)(Whi + o) = hi;
        *(uint2*)(Wlo + o) = lo;
    }
}

// ---------------- K1: chunk sums + serial chunk scan --------------------------
__global__ void k_chunksum(const float* __restrict__ in) {
    int blk = blockIdx.x;                       // b*NC + c
    int q4 = threadIdx.x * 4;
    size_t t0 = (size_t)blk * LC;
    float4 s = make_float4(0.f, 0.f, 0.f, 0.f);
    #pragma unroll 4
    for (int i = 0; i < LC; i++) {
        float4 v = ld4(in + ((t0 + i) << 10) + q4);
        s.x += v.x; s.y += v.y; s.z += v.z; s.w += v.w;
    }
    st4(buf_chunk + ((size_t)blk << 10) + q4, s);
}

__global__ void k_chunkscan() {
    int b = blockIdx.x;
    int q4 = threadIdx.x * 4;
    float4 run = make_float4(0.f, 0.f, 0.f, 0.f);
    for (int c = 0; c < NC; c++) {
        size_t idx = ((size_t)(b * NC + c) << 10) + q4;
        float4 t = ld4(buf_chunk + idx);
        st4(buf_chunk + idx, run);
        run.x += t.x; run.y += t.y; run.z += t.z; run.w += t.w;
    }
}

// ---------------- K2: fused exclusive csum + token LN + assemble x -----------
__global__ void k_csumlnx(const float* __restrict__ in,
                          const float* __restrict__ gc, const float* __restrict__ bc) {
    int blk = blockIdx.x;
    int q4 = threadIdx.x * 4;
    size_t t0 = (size_t)blk * LC;
    float4 run = ld4(buf_chunk + ((size_t)blk << 10) + q4);
    float4 g4 = ld4(gc + q4), b4 = ld4(bc + q4);
    int n = q4 >> 7, d = q4 & 127;
    for (int i = 0; i < LC; i++) {
        size_t t = t0 + i;
        float4 ip = ld4(in + (t << 10) + q4);
        float s  = run.x + run.y + run.z + run.w;
        float ss = run.x * run.x + run.y * run.y + run.z * run.z + run.w * run.w;
        block_reduce2(s, ss);
        float mu = s * (1.f / 1024.f);
        float var = ss * (1.f / 1024.f) - mu * mu;
        float rs = rsqrtf(var + EPSf);
        float4 ln;
        ln.x = (run.x - mu) * rs * g4.x + b4.x;
        ln.y = (run.y - mu) * rs * g4.y + b4.y;
        ln.z = (run.z - mu) * rs * g4.z + b4.z;
        ln.w = (run.w - mu) * rs * g4.w + b4.w;
        size_t xb = (t << 11) + n * K1c + d;
        uint2 hi, lo;
        bsplit4(ip, hi, lo);
        *(uint2*)(buf_xh + xb) = hi; *(uint2*)(buf_xl + xb) = lo;
        bsplit4(ln, hi, lo);
        *(uint2*)(buf_xh + xb + 128) = hi; *(uint2*)(buf_xl + xb + 128) = lo;
        run.x += ip.x; run.y += ip.y; run.z += ip.z; run.w += ip.w;
    }
}

// ---------------- split-bf16 mma.sync GEMM -----------------------------------
// Block tile 128x128, K-stage 32, 2-stage cp.async double buffer, 2 CTAs/SM.
// For WHICH==1 (GEMM2): A k<128 from buf_xh/xl (input half), k>=128 from cell bufs.
#define STG_BUF   10240                // 128 rows x 80B
#define STG_BYTES (4 * STG_BUF)
#define GEMM_SMEM_BYTES (2 * STG_BYTES)

template <int NTOT, int WHICH>
__global__ void __launch_bounds__(256, 2) k_gemm_mma(const float* __restrict__ bias) {
    const __nv_bfloat16* Bh = WHICH ? wt2_hi  : wt1_hi;
    const __nv_bfloat16* Bl = WHICH ? wt2_lo  : wt1_lo;
    float* Y = WHICH ? buf_og : buf_h3;

    extern __shared__ char smch[];
    const uint32_t sbase = smem_u32(smch);

    const int tid = threadIdx.x;
    const int h  = blockIdx.z;
    const int m0 = blockIdx.y * 128;
    const int n0 = blockIdx.x * 128;
    const int w = tid >> 5, lane = tid & 31;
    const int wm = w & 3, wn = w >> 2;

    float acc[2][8][4];
    #pragma unroll
    for (int i = 0; i < 2; i++)
        #pragma unroll
        for (int j = 0; j < 8; j++)
            #pragma unroll
            for (int q = 0; q < 4; q++) acc[i][j][q] = 0.f;

    auto stage = [&](int kt, int st) {
        const uint32_t sb = sbase + st * STG_BYTES;
        const int kb = kt * 32;
        #pragma unroll
        for (int g = 0; g < 2; g++) {
            int idx = tid + 256 * g;
            int row = idx >> 2, c = idx & 3;
            uint32_t soff = (uint32_t)(row * 80 + c * 16);
            const __nv_bfloat16 *pAh, *pAl;
            if (WHICH == 1 && kb >= 128) {
                size_t ga = ((size_t)(m0 + row) * Hn + h) * DOc + (kb - 128) + c * 8;
                pAh = buf_cellh + ga; pAl = buf_celll + ga;
            } else {
                size_t ga = ((size_t)(m0 + row) * Hn + h) * K1c + kb + c * 8;
                pAh = buf_xh + ga; pAl = buf_xl + ga;
            }
            CPA16(sb + soff,               pAh);
            CPA16(sb + STG_BUF + soff,     pAl);
            size_t gb = ((size_t)h * NTOT + n0 + row) * K1c + kb + c * 8;
            CPA16(sb + 2 * STG_BUF + soff, Bh + gb);
            CPA16(sb + 3 * STG_BUF + soff, Bl + gb);
        }
    };

    const int lrow = lane & 15;
    const int lhv  = lane >> 4;

    stage(0, 0);
    CPA_COMMIT;

    for (int kt = 0; kt < 8; kt++) {
        const int st = kt & 1;
        const uint32_t sb = sbase + st * STG_BYTES;
        CPA_WAIT0;
        __syncthreads();
        if (kt < 7) { stage(kt + 1, st ^ 1); CPA_COMMIT; }

        #pragma unroll
        for (int s = 0; s < 2; s++) {
            const int ch = s * 2 + lhv;
            uint32_t ah[2][4], al[2][4];
            #pragma unroll
            for (int im = 0; im < 2; im++) {
                int row = wm * 32 + im * 16 + lrow;
                uint32_t ad = sb + (uint32_t)(row * 80 + (ch << 4));
                LDSM_X4(ah[im][0], ah[im][1], ah[im][2], ah[im][3], ad);
                LDSM_X4(al[im][0], al[im][1], al[im][2], al[im][3], ad + STG_BUF);
            }
            uint32_t bh[8][2], bl[8][2];
            #pragma unroll
            for (int jn = 0; jn < 4; jn++) {
                int row = wn * 64 + jn * 16 + lrow;
                uint32_t ad = sb + 2 * STG_BUF + (uint32_t)(row * 80 + (ch << 4));
                uint32_t r0, r1, r2, r3;
                LDSM_X4(r0, r1, r2, r3, ad);
                bh[2 * jn][0] = r0; bh[2 * jn][1] = r2;
                bh[2 * jn + 1][0] = r1; bh[2 * jn + 1][1] = r3;
                LDSM_X4(r0, r1, r2, r3, ad + STG_BUF);
                bl[2 * jn][0] = r0; bl[2 * jn][1] = r2;
                bl[2 * jn + 1][0] = r1; bl[2 * jn + 1][1] = r3;
            }
            #pragma unroll
            for (int im = 0; im < 2; im++)
                #pragma unroll
                for (int jn = 0; jn < 8; jn++) {
                    MMA16816(acc[im][jn], ah[im], bh[jn]);
                    MMA16816(acc[im][jn], ah[im], bl[jn]);
                    MMA16816(acc[im][jn], al[im], bh[jn]);
                }
        }
        __syncthreads();
    }

    const int gr = lane >> 2, gc = (lane & 3) * 2;
    #pragma unroll
    for (int im = 0; im < 2; im++) {
        #pragma unroll
        for (int jn = 0; jn < 8; jn++) {
            int row = m0 + wm * 32 + im * 16 + gr;
            int col = n0 + wn * 64 + jn * 8 + gc;
            float2 bb = *(const float2*)(bias + h * NTOT + col);
            float* y0 = Y + ((size_t)row * Hn + h) * NTOT + col;
            y0[0] = acc[im][jn][0] + bb.x;
            y0[1] = acc[im][jn][1] + bb.y;
            float* y1 = Y + ((size_t)(row + 8) * Hn + h) * NTOT + col;
            y1[0] = acc[im][jn][2] + bb.x;
            y1[1] = acc[im][jn][3] + bb.y;
        }
    }
}

// ---------------- K4: fused h3-LN stats + gates + chunk (F, I) ---------------
// block = chunk of LC tokens, 256 threads x float4 = all 1024 DO dims
__global__ void k_gatescan(const float* __restrict__ gh, const float* __restrict__ bh) {
    int blk = blockIdx.x;
    int q = threadIdx.x, q4 = q * 4;
    int n = q >> 5, d = (q & 31) * 4;
    size_t t0 = (size_t)blk * LC;
    float4 gv[3], bv[3];
    #pragma unroll
    for (int g = 0; g < 3; g++) {
        gv[g] = ld4(gh + (n * 3 + g) * 128 + d);
        bv[g] = ld4(bh + (n * 3 + g) * 128 + d);
    }
    float4 F = make_float4(1.f, 1.f, 1.f, 1.f);
    float4 I = make_float4(0.f, 0.f, 0.f, 0.f);
    for (int i = 0; i < LC; i++) {
        size_t t = t0 + i;
        const float* hp = buf_h3 + t * (Hn * N1c) + n * N1c + d;
        float4 xi = ld4(hp), xf = ld4(hp + 128), xv = ld4(hp + 256);
        float s  = xi.x + xi.y + xi.z + xi.w + xf.x + xf.y + xf.z + xf.w
                 + xv.x + xv.y + xv.z + xv.w;
        float ss = xi.x*xi.x + xi.y*xi.y + xi.z*xi.z + xi.w*xi.w
                 + xf.x*xf.x + xf.y*xf.y + xf.z*xf.z + xf.w*xf.w
                 + xv.x*xv.x + xv.y*xv.y + xv.z*xv.z + xv.w*xv.w;
        block_reduce2(s, ss);
        float mu  = s * (1.f / 3072.f);
        float var = ss * (1.f / 3072.f) - mu * mu;
        float rs  = rsqrtf(var + EPSf);
        if (q == 0) buf_stats[t] = make_float2(mu, rs);
        float4 fg, ih;
        fg.x = sigm((xf.x - mu) * rs * gv[1].x + bv[1].x);
        fg.y = sigm((xf.y - mu) * rs * gv[1].y + bv[1].y);
        fg.z = sigm((xf.z - mu) * rs * gv[1].z + bv[1].z);
        fg.w = sigm((xf.w - mu) * rs * gv[1].w + bv[1].w);
        ih.x = sigm((xi.x - mu) * rs * gv[0].x + bv[0].x) * fmaxf((xv.x - mu) * rs * gv[2].x + bv[2].x, 0.f);
        ih.y = sigm((xi.y - mu) * rs * gv[0].y + bv[0].y) * fmaxf((xv.y - mu) * rs * gv[2].y + bv[2].y, 0.f);
        ih.z = sigm((xi.z - mu) * rs * gv[0].z + bv[0].z) * fmaxf((xv.z - mu) * rs * gv[2].z + bv[2].z, 0.f);
        ih.w = sigm((xi.w - mu) * rs * gv[0].w + bv[0].w) * fmaxf((xv.w - mu) * rs * gv[2].w + bv[2].w, 0.f);
        F.x *= fg.x; F.y *= fg.y; F.z *= fg.z; F.w *= fg.w;
        I.x = fg.x * I.x + ih.x; I.y = fg.y * I.y + ih.y;
        I.z = fg.z * I.z + ih.z; I.w = fg.w * I.w + ih.w;
    }
    st4(buf_Fc + ((size_t)blk << 10) + q4, F);
    st4(buf_Ic + ((size_t)blk << 10) + q4, I);
}

// ---------------- K5: inter-chunk scan ---------------------------------------
__global__ void k_scanB(const float* __restrict__ init_cx) {
    int b = blockIdx.x;
    int q4 = threadIdx.x * 4;
    float4 c0 = ld4(init_cx + q4);
    for (int c = 0; c < NC; c++) {
        size_t idx = ((size_t)(b * NC + c) << 10) + q4;
        st4(buf_cst + idx, c0);
        float4 F = ld4(buf_Fc + idx), I = ld4(buf_Ic + idx);
        c0.x = F.x * c0.x + I.x; c0.y = F.y * c0.y + I.y;
        c0.z = F.z * c0.z + I.z; c0.w = F.w * c0.w + I.w;
    }
}

// ---------------- K6: recompute gates from h3+stats, scan cell, write cell ---
__global__ void k_scanC(const float* __restrict__ gh, const float* __restrict__ bh) {
    int blk = blockIdx.x;
    int q = threadIdx.x, q4 = q * 4;
    int n = q >> 5, d = (q & 31) * 4;
    size_t t0 = (size_t)blk * LC;
    float4 gv[3], bv[3];
    #pragma unroll
    for (int g = 0; g < 3; g++) {
        gv[g] = ld4(gh + (n * 3 + g) * 128 + d);
        bv[g] = ld4(bh + (n * 3 + g) * 128 + d);
    }
    float4 cc = ld4(buf_cst + ((size_t)blk << 10) + q4);
    for (int i = 0; i < LC; i++) {
        size_t t = t0 + i;
        float2 st2 = buf_stats[t];
        float mu = st2.x, rs = st2.y;
        const float* hp = buf_h3 + t * (Hn * N1c) + n * N1c + d;
        float4 xi = ld4(hp), xf = ld4(hp + 128), xv = ld4(hp + 256);
        float4 fg, ih;
        fg.x = sigm((xf.x - mu) * rs * gv[1].x + bv[1].x);
        fg.y = sigm((xf.y - mu) * rs * gv[1].y + bv[1].y);
        fg.z = sigm((xf.z - mu) * rs * gv[1].z + bv[1].z);
        fg.w = sigm((xf.w - mu) * rs * gv[1].w + bv[1].w);
        ih.x = sigm((xi.x - mu) * rs * gv[0].x + bv[0].x) * fmaxf((xv.x - mu) * rs * gv[2].x + bv[2].x, 0.f);
        ih.y = sigm((xi.y - mu) * rs * gv[0].y + bv[0].y) * fmaxf((xv.y - mu) * rs * gv[2].y + bv[2].y, 0.f);
        ih.z = sigm((xi.z - mu) * rs * gv[0].z + bv[0].z) * fmaxf((xv.z - mu) * rs * gv[2].z + bv[2].z, 0.f);
        ih.w = sigm((xi.w - mu) * rs * gv[0].w + bv[0].w) * fmaxf((xv.w - mu) * rs * gv[2].w + bv[2].w, 0.f);
        cc.x = fg.x * cc.x + ih.x; cc.y = fg.y * cc.y + ih.y;
        cc.z = fg.z * cc.z + ih.z; cc.w = fg.w * cc.w + ih.w;
        uint2 hi, lo;
        bsplit4(cc, hi, lo);
        *(uint2*)(buf_cellh + (t << 10) + q4) = hi;
        *(uint2*)(buf_celll + (t << 10) + q4) = lo;
    }
}

// ---------------- K7: token LN of og (1024) + sigmoid * cell -----------------
__global__ void k_out(const float* __restrict__ gg, const float* __restrict__ bg,
                      float* __restrict__ out) {
    int t = blockIdx.x;
    int i = threadIdx.x * 4;
    float4 o4 = ld4(buf_og + ((size_t)t << 10) + i);
    float s  = o4.x + o4.y + o4.z + o4.w;
    float ss = o4.x * o4.x + o4.y * o4.y + o4.z * o4.z + o4.w * o4.w;
    block_reduce2(s, ss);
    float mu  = s * (1.f / 1024.f);
    float var = ss * (1.f / 1024.f) - mu * mu;
    float rs  = rsqrtf(var + EPSf);
    float4 g4 = ld4(gg + i), b4 = ld4(bg + i);
    float4 cell = bunpack4(*(const uint2*)(buf_cellh + ((size_t)t << 10) + i),
                           *(const uint2*)(buf_celll + ((size_t)t << 10) + i));
    float4 r;
    r.x = cell.x * sigm((o4.x - mu) * rs * g4.x + b4.x);
    r.y = cell.y * sigm((o4.y - mu) * rs * g4.y + b4.y);
    r.z = cell.z * sigm((o4.z - mu) * rs * g4.z + b4.z);
    r.w = cell.w * sigm((o4.w - mu) * rs * g4.w + b4.w);
    st4(out + ((size_t)t << 10) + i, r);
}

// ---------------- launch ------------------------------------------------------
extern "C" void kernel_launch(void* const* d_in, const int* in_sizes, int n_in,
                              void* d_out, int out_size) {
    const float* heads_input = (const float*)d_in[0];
    const float* W_hid       = (const float*)d_in[1];
    const float* b_hid       = (const float*)d_in[2];
    const float* g_csum      = (const float*)d_in[3];
    const float* beta_csum   = (const float*)d_in[4];
    const float* g_hid       = (const float*)d_in[5];
    const float* beta_hid    = (const float*)d_in[6];
    const float* W_og        = (const float*)d_in[7];
    const float* b_og        = (const float*)d_in[8];
    const float* g_og        = (const float*)d_in[9];
    const float* beta_og     = (const float*)d_in[10];
    const float* init_cx     = (const float*)d_in[11];
    float* out = (float*)d_out;

    cudaFuncSetAttribute(k_gemm_mma<N1c, 0>,
        cudaFuncAttributeMaxDynamicSharedMemorySize, GEMM_SMEM_BYTES);
    cudaFuncSetAttribute(k_gemm_mma<N2c, 1>,
        cudaFuncAttributeMaxDynamicSharedMemorySize, GEMM_SMEM_BYTES);

    // 0) weight transpose + bf16 split
    k_wsplit<0><<<dim3(N1c / 32, K1c / 32, Hn), 256>>>(W_hid);
    k_wsplit<1><<<dim3(N2c / 32, K1c / 32, Hn), 256>>>(W_og);
    // 1) chunk sums + serial scan over chunks
    k_chunksum<<<Bsz * NC, 256>>>(heads_input);
    k_chunkscan<<<Bsz, 256>>>();
    // 2) fused exclusive csum + LN + build x (bf16 hi/lo)
    k_csumlnx<<<Bsz * NC, 256>>>(heads_input, g_csum, beta_csum);
    // 3) GEMM1 (split-bf16 mma.sync): per-head (16384 x 384 x 256)
    k_gemm_mma<N1c, 0><<<dim3(N1c / 128, Tsz / 128, Hn), 256, GEMM_SMEM_BYTES>>>(b_hid);
    // 4) fused LN stats + gates + chunk (F,I)
    k_gatescan<<<Bsz * NC, 256>>>(g_hid, beta_hid);
    // 5) inter-chunk scan
    k_scanB<<<Bsz, 256>>>(init_cx);
    // 6) recompute gates + scan cell + write cell (bf16 hi/lo)
    k_scanC<<<Bsz * NC, 256>>>(g_hid, beta_hid);
    // 7) GEMM2 (split-bf16 mma.sync): per-head (16384 x 128 x 256)
    k_gemm_mma<N2c, 1><<<dim3(N2c / 128, Tsz / 128, Hn), 256, GEMM_SMEM_BYTES>>>(b_og);
    // 8) final LN + sigmoid*cell
    k_out<<<Tsz, 256>>>(g_og, beta_og, out);
}

// round 14
// speedup vs baseline: 1.1154x; 1.1154x over previous
#include <cuda_runtime.h>
#include <cuda_bf16.h>
#include <math.h>
#include <cstdint>

// Problem constants
#define Bsz 4
#define Ssz 4096
#define Hn  8
#define DIc 128
#define DOc 128
#define Tsz (Bsz*Ssz)        // 16384 tokens
#define K1c 256              // 2*DI
#define N1c 384              // 3*DO
#define N2c 128
#define NC  128              // scan chunks
#define LC  (Ssz/NC)         // 32 steps per chunk
#define EPSf 1e-6f

// ---------------- static scratch (device globals; no allocation) -------------
__device__ __align__(16) __nv_bfloat16 buf_xh [(size_t)Tsz*Hn*K1c];  // A1 hi ([in, ln(csum)])
__device__ __align__(16) __nv_bfloat16 buf_xl [(size_t)Tsz*Hn*K1c];  // A1 lo
__device__ __align__(16) __nv_bfloat16 buf_cellh[(size_t)Tsz*Hn*DOc]; // cell hi
__device__ __align__(16) __nv_bfloat16 buf_celll[(size_t)Tsz*Hn*DOc]; // cell lo
__device__ float buf_h3  [(size_t)Tsz*Hn*N1c];
__device__ float buf_og  [(size_t)Tsz*Hn*DOc];
__device__ float buf_chunk[Bsz*NC*Hn*DIc];
__device__ float buf_Fc  [Bsz*NC*Hn*DOc];
__device__ float buf_Ic  [Bsz*NC*Hn*DOc];
__device__ float buf_cst [Bsz*NC*Hn*DOc];
__device__ float2 buf_stats[Tsz];            // (mu, rs) of h3 LN per token
// pre-split / transposed weights: [h][n][k] bf16 hi/lo
__device__ __align__(16) __nv_bfloat16 wt1_hi[(size_t)Hn*N1c*K1c];
__device__ __align__(16) __nv_bfloat16 wt1_lo[(size_t)Hn*N1c*K1c];
__device__ __align__(16) __nv_bfloat16 wt2_hi[(size_t)Hn*N2c*K1c];
__device__ __align__(16) __nv_bfloat16 wt2_lo[(size_t)Hn*N2c*K1c];

// ---------------- PTX helpers -------------------------------------------------
__device__ __forceinline__ uint32_t smem_u32(const void* p) {
    uint32_t a;
    asm("{ .reg .u64 t; cvta.to.shared.u64 t, %1; cvt.u32.u64 %0, t; }" : "=r"(a) : "l"(p));
    return a;
}
#define CPA16(sm_addr, gm_ptr) \
    asm volatile("cp.async.cg.shared.global [%0], [%1], 16;" \
                 :: "r"(sm_addr), "l"(gm_ptr) : "memory")
#define CPA_COMMIT asm volatile("cp.async.commit_group;" ::: "memory")
#define CPA_WAIT0  asm volatile("cp.async.wait_group 0;"  ::: "memory")

#define LDSM_X4(r0,r1,r2,r3,addr) \
    asm volatile("ldmatrix.sync.aligned.m8n8.x4.shared.b16 {%0,%1,%2,%3},[%4];" \
                 : "=r"(r0),"=r"(r1),"=r"(r2),"=r"(r3) : "r"(addr))

#define MMA16816(d, a, b) \
    asm volatile("mma.sync.aligned.m16n8k16.row.col.f32.bf16.bf16.f32 " \
                 "{%0,%1,%2,%3},{%4,%5,%6,%7},{%8,%9},{%0,%1,%2,%3};" \
                 : "+f"((d)[0]),"+f"((d)[1]),"+f"((d)[2]),"+f"((d)[3]) \
                 : "r"((a)[0]),"r"((a)[1]),"r"((a)[2]),"r"((a)[3]), \
                   "r"((b)[0]),"r"((b)[1]))

__device__ __forceinline__ void bsplit(float v, __nv_bfloat16& hi, __nv_bfloat16& lo) {
    hi = __float2bfloat16_rn(v);
    lo = __float2bfloat16_rn(v - __bfloat162float(hi));
}
__device__ __forceinline__ void bsplit4(float4 v, uint2& hi, uint2& lo) {
    __nv_bfloat16 h0,l0,h1,l1,h2,l2,h3,l3;
    bsplit(v.x,h0,l0); bsplit(v.y,h1,l1); bsplit(v.z,h2,l2); bsplit(v.w,h3,l3);
    hi.x = (uint32_t)__bfloat16_as_ushort(h0) | ((uint32_t)__bfloat16_as_ushort(h1) << 16);
    hi.y = (uint32_t)__bfloat16_as_ushort(h2) | ((uint32_t)__bfloat16_as_ushort(h3) << 16);
    lo.x = (uint32_t)__bfloat16_as_ushort(l0) | ((uint32_t)__bfloat16_as_ushort(l1) << 16);
    lo.y = (uint32_t)__bfloat16_as_ushort(l2) | ((uint32_t)__bfloat16_as_ushort(l3) << 16);
}
__device__ __forceinline__ float4 bunpack4(uint2 h, uint2 l) {
    float4 r;
    r.x = __bfloat162float(__ushort_as_bfloat16((unsigned short)(h.x & 0xffff)))
        + __bfloat162float(__ushort_as_bfloat16((unsigned short)(l.x & 0xffff)));
    r.y = __bfloat162float(__ushort_as_bfloat16((unsigned short)(h.x >> 16)))
        + __bfloat162float(__ushort_as_bfloat16((unsigned short)(l.x >> 16)));
    r.z = __bfloat162float(__ushort_as_bfloat16((unsigned short)(h.y & 0xffff)))
        + __bfloat162float(__ushort_as_bfloat16((unsigned short)(l.y & 0xffff)));
    r.w = __bfloat162float(__ushort_as_bfloat16((unsigned short)(h.y >> 16)))
        + __bfloat162float(__ushort_as_bfloat16((unsigned short)(l.y >> 16)));
    return r;
}
__device__ __forceinline__ float4 ld4(const float* p) { return *(const float4*)p; }
__device__ __forceinline__ void st4(float* p, float4 v) { *(float4*)p = v; }

// ---------------- helpers ----------------------------------------------------
// loop-safe (trailing barrier so shared slots can be reused next call)
__device__ __forceinline__ void block_reduce2(float& s, float& ss) {
    __shared__ float shs[32], shss[32];
    #pragma unroll
    for (int o = 16; o > 0; o >>= 1) {
        s  += __shfl_down_sync(0xffffffffu, s,  o);
        ss += __shfl_down_sync(0xffffffffu, ss, o);
    }
    int lane = threadIdx.x & 31, w = threadIdx.x >> 5, nw = blockDim.x >> 5;
    if (lane == 0) { shs[w] = s; shss[w] = ss; }
    __syncthreads();
    if (w == 0) {
        s  = (lane < nw) ? shs[lane]  : 0.f;
        ss = (lane < nw) ? shss[lane] : 0.f;
        #pragma unroll
        for (int o = 16; o > 0; o >>= 1) {
            s  += __shfl_down_sync(0xffffffffu, s,  o);
            ss += __shfl_down_sync(0xffffffffu, ss, o);
        }
        if (lane == 0) { shs[0] = s; shss[0] = ss; }
    }
    __syncthreads();
    s = shs[0]; ss = shss[0];
    __syncthreads();
}

__device__ __forceinline__ float sigm(float x) { return 1.f / (1.f + expf(-x)); }

// ---------------- K0: weight transpose + bf16 split (smem tiled) -------------
template <int WHICH>
__global__ void k_wsplit(const float* __restrict__ W) {
    const int N = (WHICH == 0) ? N1c : N2c;
    __nv_bfloat16* Whi = (WHICH == 0) ? wt1_hi : wt2_hi;
    __nv_bfloat16* Wlo = (WHICH == 0) ? wt1_lo : wt2_lo;
    __shared__ float tile[32][33];
    const int n0 = blockIdx.x * 32, k0 = blockIdx.y * 32, hh = blockIdx.z;
    const int tid = threadIdx.x;
    {
        int r = tid >> 3, cq = tid & 7;
        float4 v = ld4(W + ((size_t)hh * K1c + k0 + r) * N + n0 + cq * 4);
        tile[r][cq * 4 + 0] = v.x; tile[r][cq * 4 + 1] = v.y;
        tile[r][cq * 4 + 2] = v.z; tile[r][cq * 4 + 3] = v.w;
    }
    __syncthreads();
    {
        int nr = tid >> 3, kq = tid & 7;
        float4 v;
        v.x = tile[kq * 4 + 0][nr]; v.y = tile[kq * 4 + 1][nr];
        v.z = tile[kq * 4 + 2][nr]; v.w = tile[kq * 4 + 3][nr];
        uint2 hi, lo;
        bsplit4(v, hi, lo);
        size_t o = ((size_t)hh * N + n0 + nr) * K1c + k0 + kq * 4;
        *(uint2*)(Whi + o) = hi;
        *(uint2*)(Wlo + o) = lo;
    }
}

// ---------------- K1: chunk sums + serial chunk scan --------------------------
__global__ void k_chunksum(const float* __restrict__ in) {
    int blk = blockIdx.x;                       // b*NC + c
    int q4 = threadIdx.x * 4;
    size_t t0 = (size_t)blk * LC;
    float4 s = make_float4(0.f, 0.f, 0.f, 0.f);
    #pragma unroll 4
    for (int i = 0; i < LC; i++) {
        float4 v = ld4(in + ((t0 + i) << 10) + q4);
        s.x += v.x; s.y += v.y; s.z += v.z; s.w += v.w;
    }
    st4(buf_chunk + ((size_t)blk << 10) + q4, s);
}

__global__ void k_chunkscan() {
    int b = blockIdx.x;
    int q4 = threadIdx.x * 4;
    float4 run = make_float4(0.f, 0.f, 0.f, 0.f);
    float4 t = ld4(buf_chunk + ((size_t)(b * NC) << 10) + q4);
    for (int c = 0; c < NC; c++) {
        size_t idx = ((size_t)(b * NC + c) << 10) + q4;
        float4 tn;
        if (c + 1 < NC) tn = ld4(buf_chunk + idx + 1024);   // prefetch
        st4(buf_chunk + idx, run);
        run.x += t.x; run.y += t.y; run.z += t.z; run.w += t.w;
        t = tn;
    }
}

// ---------------- K2: fused exclusive csum + token LN + assemble x -----------
__global__ void k_csumlnx(const float* __restrict__ in,
                          const float* __restrict__ gc, const float* __restrict__ bc) {
    int blk = blockIdx.x;
    int q4 = threadIdx.x * 4;
    size_t t0 = (size_t)blk * LC;
    float4 run = ld4(buf_chunk + ((size_t)blk << 10) + q4);
    float4 g4 = ld4(gc + q4), b4 = ld4(bc + q4);
    int n = q4 >> 7, d = q4 & 127;
    float4 ip = ld4(in + (t0 << 10) + q4);
    for (int i = 0; i < LC; i++) {
        size_t t = t0 + i;
        float4 ipn;
        if (i + 1 < LC) ipn = ld4(in + ((t + 1) << 10) + q4);  // prefetch before barriers
        float s  = run.x + run.y + run.z + run.w;
        float ss = run.x * run.x + run.y * run.y + run.z * run.z + run.w * run.w;
        block_reduce2(s, ss);
        float mu = s * (1.f / 1024.f);
        float var = ss * (1.f / 1024.f) - mu * mu;
        float rs = rsqrtf(var + EPSf);
        float4 ln;
        ln.x = (run.x - mu) * rs * g4.x + b4.x;
        ln.y = (run.y - mu) * rs * g4.y + b4.y;
        ln.z = (run.z - mu) * rs * g4.z + b4.z;
        ln.w = (run.w - mu) * rs * g4.w + b4.w;
        size_t xb = (t << 11) + n * K1c + d;
        uint2 hi, lo;
        bsplit4(ip, hi, lo);
        *(uint2*)(buf_xh + xb) = hi; *(uint2*)(buf_xl + xb) = lo;
        bsplit4(ln, hi, lo);
        *(uint2*)(buf_xh + xb + 128) = hi; *(uint2*)(buf_xl + xb + 128) = lo;
        run.x += ip.x; run.y += ip.y; run.z += ip.z; run.w += ip.w;
        ip = ipn;
    }
}

// ---------------- split-bf16 mma.sync GEMM -----------------------------------
// Block tile 128x128, K-stage 32, 2-stage cp.async double buffer, 2 CTAs/SM.
// For WHICH==1 (GEMM2): A k<128 from buf_xh/xl (input half), k>=128 from cell bufs.
#define STG_BUF   10240                // 128 rows x 80B
#define STG_BYTES (4 * STG_BUF)
#define GEMM_SMEM_BYTES (2 * STG_BYTES)

template <int NTOT, int WHICH>
__global__ void __launch_bounds__(256, 2) k_gemm_mma(const float* __restrict__ bias) {
    const __nv_bfloat16* Bh = WHICH ? wt2_hi  : wt1_hi;
    const __nv_bfloat16* Bl = WHICH ? wt2_lo  : wt1_lo;
    float* Y = WHICH ? buf_og : buf_h3;

    extern __shared__ char smch[];
    const uint32_t sbase = smem_u32(smch);

    const int tid = threadIdx.x;
    const int h  = blockIdx.z;
    const int m0 = blockIdx.y * 128;
    const int n0 = blockIdx.x * 128;
    const int w = tid >> 5, lane = tid & 31;
    const int wm = w & 3, wn = w >> 2;

    float acc[2][8][4];
    #pragma unroll
    for (int i = 0; i < 2; i++)
        #pragma unroll
        for (int j = 0; j < 8; j++)
            #pragma unroll
            for (int q = 0; q < 4; q++) acc[i][j][q] = 0.f;

    auto stage = [&](int kt, int st) {
        const uint32_t sb = sbase + st * STG_BYTES;
        const int kb = kt * 32;
        #pragma unroll
        for (int g = 0; g < 2; g++) {
            int idx = tid + 256 * g;
            int row = idx >> 2, c = idx & 3;
            uint32_t soff = (uint32_t)(row * 80 + c * 16);
            const __nv_bfloat16 *pAh, *pAl;
            if (WHICH == 1 && kb >= 128) {
                size_t ga = ((size_t)(m0 + row) * Hn + h) * DOc + (kb - 128) + c * 8;
                pAh = buf_cellh + ga; pAl = buf_celll + ga;
            } else {
                size_t ga = ((size_t)(m0 + row) * Hn + h) * K1c + kb + c * 8;
                pAh = buf_xh + ga; pAl = buf_xl + ga;
            }
            CPA16(sb + soff,               pAh);
            CPA16(sb + STG_BUF + soff,     pAl);
            size_t gb = ((size_t)h * NTOT + n0 + row) * K1c + kb + c * 8;
            CPA16(sb + 2 * STG_BUF + soff, Bh + gb);
            CPA16(sb + 3 * STG_BUF + soff, Bl + gb);
        }
    };

    const int lrow = lane & 15;
    const int lhv  = lane >> 4;

    stage(0, 0);
    CPA_COMMIT;

    for (int kt = 0; kt < 8; kt++) {
        const int st = kt & 1;
        const uint32_t sb = sbase + st * STG_BYTES;
        CPA_WAIT0;
        __syncthreads();
        if (kt < 7) { stage(kt + 1, st ^ 1); CPA_COMMIT; }

        #pragma unroll
        for (int s = 0; s < 2; s++) {
            const int ch = s * 2 + lhv;
            uint32_t ah[2][4], al[2][4];
            #pragma unroll
            for (int im = 0; im < 2; im++) {
                int row = wm * 32 + im * 16 + lrow;
                uint32_t ad = sb + (uint32_t)(row * 80 + (ch << 4));
                LDSM_X4(ah[im][0], ah[im][1], ah[im][2], ah[im][3], ad);
                LDSM_X4(al[im][0], al[im][1], al[im][2], al[im][3], ad + STG_BUF);
            }
            uint32_t bh[8][2], bl[8][2];
            #pragma unroll
            for (int jn = 0; jn < 4; jn++) {
                int row = wn * 64 + jn * 16 + lrow;
                uint32_t ad = sb + 2 * STG_BUF + (uint32_t)(row * 80 + (ch << 4));
                uint32_t r0, r1, r2, r3;
                LDSM_X4(r0, r1, r2, r3, ad);
                bh[2 * jn][0] = r0; bh[2 * jn][1] = r2;
                bh[2 * jn + 1][0] = r1; bh[2 * jn + 1][1] = r3;
                LDSM_X4(r0, r1, r2, r3, ad + STG_BUF);
                bl[2 * jn][0] = r0; bl[2 * jn][1] = r2;
                bl[2 * jn + 1][0] = r1; bl[2 * jn + 1][1] = r3;
            }
            #pragma unroll
            for (int im = 0; im < 2; im++)
                #pragma unroll
                for (int jn = 0; jn < 8; jn++) {
                    MMA16816(acc[im][jn], ah[im], bh[jn]);
                    MMA16816(acc[im][jn], ah[im], bl[jn]);
                    MMA16816(acc[im][jn], al[im], bh[jn]);
                }
        }
        __syncthreads();
    }

    const int gr = lane >> 2, gc = (lane & 3) * 2;
    #pragma unroll
    for (int im = 0; im < 2; im++) {
        #pragma unroll
        for (int jn = 0; jn < 8; jn++) {
            int row = m0 + wm * 32 + im * 16 + gr;
            int col = n0 + wn * 64 + jn * 8 + gc;
            float2 bb = *(const float2*)(bias + h * NTOT + col);
            float* y0 = Y + ((size_t)row * Hn + h) * NTOT + col;
            y0[0] = acc[im][jn][0] + bb.x;
            y0[1] = acc[im][jn][1] + bb.y;
            float* y1 = Y + ((size_t)(row + 8) * Hn + h) * NTOT + col;
            y1[0] = acc[im][jn][2] + bb.x;
            y1[1] = acc[im][jn][3] + bb.y;
        }
    }
}

// ---------------- K4: fused h3-LN stats + gates + chunk (F, I) ---------------
__global__ void k_gatescan(const float* __restrict__ gh, const float* __restrict__ bh) {
    int blk = blockIdx.x;
    int q = threadIdx.x, q4 = q * 4;
    int n = q >> 5, d = (q & 31) * 4;
    size_t t0 = (size_t)blk * LC;
    float4 gv[3], bv[3];
    #pragma unroll
    for (int g = 0; g < 3; g++) {
        gv[g] = ld4(gh + (n * 3 + g) * 128 + d);
        bv[g] = ld4(bh + (n * 3 + g) * 128 + d);
    }
    float4 F = make_float4(1.f, 1.f, 1.f, 1.f);
    float4 I = make_float4(0.f, 0.f, 0.f, 0.f);
    const float* hp0 = buf_h3 + t0 * (Hn * N1c) + n * N1c + d;
    float4 xi = ld4(hp0), xf = ld4(hp0 + 128), xv = ld4(hp0 + 256);
    for (int i = 0; i < LC; i++) {
        size_t t = t0 + i;
        float4 xin, xfn, xvn;
        if (i + 1 < LC) {                       // prefetch before barriers
            const float* hp = buf_h3 + (t + 1) * (Hn * N1c) + n * N1c + d;
            xin = ld4(hp); xfn = ld4(hp + 128); xvn = ld4(hp + 256);
        }
        float s  = xi.x + xi.y + xi.z + xi.w + xf.x + xf.y + xf.z + xf.w
                 + xv.x + xv.y + xv.z + xv.w;
        float ss = xi.x*xi.x + xi.y*xi.y + xi.z*xi.z + xi.w*xi.w
                 + xf.x*xf.x + xf.y*xf.y + xf.z*xf.z + xf.w*xf.w
                 + xv.x*xv.x + xv.y*xv.y + xv.z*xv.z + xv.w*xv.w;
        block_reduce2(s, ss);
        float mu  = s * (1.f / 3072.f);
        float var = ss * (1.f / 3072.f) - mu * mu;
        float rs  = rsqrtf(var + EPSf);
        if (q == 0) buf_stats[t] = make_float2(mu, rs);
        float4 fg, ih;
        fg.x = sigm((xf.x - mu) * rs * gv[1].x + bv[1].x);
        fg.y = sigm((xf.y - mu) * rs * gv[1].y + bv[1].y);
        fg.z = sigm((xf.z - mu) * rs * gv[1].z + bv[1].z);
        fg.w = sigm((xf.w - mu) * rs * gv[1].w + bv[1].w);
        ih.x = sigm((xi.x - mu) * rs * gv[0].x + bv[0].x) * fmaxf((xv.x - mu) * rs * gv[2].x + bv[2].x, 0.f);
        ih.y = sigm((xi.y - mu) * rs * gv[0].y + bv[0].y) * fmaxf((xv.y - mu) * rs * gv[2].y + bv[2].y, 0.f);
        ih.z = sigm((xi.z - mu) * rs * gv[0].z + bv[0].z) * fmaxf((xv.z - mu) * rs * gv[2].z + bv[2].z, 0.f);
        ih.w = sigm((xi.w - mu) * rs * gv[0].w + bv[0].w) * fmaxf((xv.w - mu) * rs * gv[2].w + bv[2].w, 0.f);
        F.x *= fg.x; F.y *= fg.y; F.z *= fg.z; F.w *= fg.w;
        I.x = fg.x * I.x + ih.x; I.y = fg.y * I.y + ih.y;
        I.z = fg.z * I.z + ih.z; I.w = fg.w * I.w + ih.w;
        xi = xin; xf = xfn; xv = xvn;
    }
    st4(buf_Fc + ((size_t)blk << 10) + q4, F);
    st4(buf_Ic + ((size_t)blk << 10) + q4, I);
}

// ---------------- K5: inter-chunk scan ---------------------------------------
__global__ void k_scanB(const float* __restrict__ init_cx) {
    int b = blockIdx.x;
    int q4 = threadIdx.x * 4;
    float4 c0 = ld4(init_cx + q4);
    size_t i0 = ((size_t)(b * NC) << 10) + q4;
    float4 F = ld4(buf_Fc + i0), I = ld4(buf_Ic + i0);
    for (int c = 0; c < NC; c++) {
        size_t idx = ((size_t)(b * NC + c) << 10) + q4;
        float4 Fn, In;
        if (c + 1 < NC) { Fn = ld4(buf_Fc + idx + 1024); In = ld4(buf_Ic + idx + 1024); }
        st4(buf_cst + idx, c0);
        c0.x = F.x * c0.x + I.x; c0.y = F.y * c0.y + I.y;
        c0.z = F.z * c0.z + I.z; c0.w = F.w * c0.w + I.w;
        F = Fn; I = In;
    }
}

// ---------------- K6: recompute gates from h3+stats, scan cell, write cell ---
__global__ void k_scanC(const float* __restrict__ gh, const float* __restrict__ bh) {
    int blk = blockIdx.x;
    int q = threadIdx.x, q4 = q * 4;
    int n = q >> 5, d = (q & 31) * 4;
    size_t t0 = (size_t)blk * LC;
    float4 gv[3], bv[3];
    #pragma unroll
    for (int g = 0; g < 3; g++) {
        gv[g] = ld4(gh + (n * 3 + g) * 128 + d);
        bv[g] = ld4(bh + (n * 3 + g) * 128 + d);
    }
    float4 cc = ld4(buf_cst + ((size_t)blk << 10) + q4);
    const float* hp0 = buf_h3 + t0 * (Hn * N1c) + n * N1c + d;
    float4 xi = ld4(hp0), xf = ld4(hp0 + 128), xv = ld4(hp0 + 256);
    float2 st2 = buf_stats[t0];
    for (int i = 0; i < LC; i++) {
        size_t t = t0 + i;
        float4 xin, xfn, xvn; float2 stn;
        if (i + 1 < LC) {                       // prefetch
            const float* hp = buf_h3 + (t + 1) * (Hn * N1c) + n * N1c + d;
            xin = ld4(hp); xfn = ld4(hp + 128); xvn = ld4(hp + 256);
            stn = buf_stats[t + 1];
        }
        float mu = st2.x, rs = st2.y;
        float4 fg, ih;
        fg.x = sigm((xf.x - mu) * rs * gv[1].x + bv[1].x);
        fg.y = sigm((xf.y - mu) * rs * gv[1].y + bv[1].y);
        fg.z = sigm((xf.z - mu) * rs * gv[1].z + bv[1].z);
        fg.w = sigm((xf.w - mu) * rs * gv[1].w + bv[1].w);
        ih.x = sigm((xi.x - mu) * rs * gv[0].x + bv[0].x) * fmaxf((xv.x - mu) * rs * gv[2].x + bv[2].x, 0.f);
        ih.y = sigm((xi.y - mu) * rs * gv[0].y + bv[0].y) * fmaxf((xv.y - mu) * rs * gv[2].y + bv[2].y, 0.f);
        ih.z = sigm((xi.z - mu) * rs * gv[0].z + bv[0].z) * fmaxf((xv.z - mu) * rs * gv[2].z + bv[2].z, 0.f);
        ih.w = sigm((xi.w - mu) * rs * gv[0].w + bv[0].w) * fmaxf((xv.w - mu) * rs * gv[2].w + bv[2].w, 0.f);
        cc.x = fg.x * cc.x + ih.x; cc.y = fg.y * cc.y + ih.y;
        cc.z = fg.z * cc.z + ih.z; cc.w = fg.w * cc.w + ih.w;
        uint2 hi, lo;
        bsplit4(cc, hi, lo);
        *(uint2*)(buf_cellh + (t << 10) + q4) = hi;
        *(uint2*)(buf_celll + (t << 10) + q4) = lo;
        xi = xin; xf = xfn; xv = xvn; st2 = stn;
    }
}

// ---------------- K7: token LN of og (1024) + sigmoid * cell -----------------
__global__ void k_out(const float* __restrict__ gg, const float* __restrict__ bg,
                      float* __restrict__ out) {
    int t = blockIdx.x;
    int i = threadIdx.x * 4;
    float4 o4 = ld4(buf_og + ((size_t)t << 10) + i);
    float s  = o4.x + o4.y + o4.z + o4.w;
    float ss = o4.x * o4.x + o4.y * o4.y + o4.z * o4.z + o4.w * o4.w;
    block_reduce2(s, ss);
    float mu  = s * (1.f / 1024.f);
    float var = ss * (1.f / 1024.f) - mu * mu;
    float rs  = rsqrtf(var + EPSf);
    float4 g4 = ld4(gg + i), b4 = ld4(bg + i);
    float4 cell = bunpack4(*(const uint2*)(buf_cellh + ((size_t)t << 10) + i),
                           *(const uint2*)(buf_celll + ((size_t)t << 10) + i));
    float4 r;
    r.x = cell.x * sigm((o4.x - mu) * rs * g4.x + b4.x);
    r.y = cell.y * sigm((o4.y - mu) * rs * g4.y + b4.y);
    r.z = cell.z * sigm((o4.z - mu) * rs * g4.z + b4.z);
    r.w = cell.w * sigm((o4.w - mu) * rs * g4.w + b4.w);
    st4(out + ((size_t)t << 10) + i, r);
}

// ---------------- launch ------------------------------------------------------
extern "C" void kernel_launch(void* const* d_in, const int* in_sizes, int n_in,
                              void* d_out, int out_size) {
    const float* heads_input = (const float*)d_in[0];
    const float* W_hid       = (const float*)d_in[1];
    const float* b_hid       = (const float*)d_in[2];
    const float* g_csum      = (const float*)d_in[3];
    const float* beta_csum   = (const float*)d_in[4];
    const float* g_hid       = (const float*)d_in[5];
    const float* beta_hid    = (const float*)d_in[6];
    const float* W_og        = (const float*)d_in[7];
    const float* b_og        = (const float*)d_in[8];
    const float* g_og        = (const float*)d_in[9];
    const float* beta_og     = (const float*)d_in[10];
    const float* init_cx     = (const float*)d_in[11];
    float* out = (float*)d_out;

    cudaFuncSetAttribute(k_gemm_mma<N1c, 0>,
        cudaFuncAttributeMaxDynamicSharedMemorySize, GEMM_SMEM_BYTES);
    cudaFuncSetAttribute(k_gemm_mma<N2c, 1>,
        cudaFuncAttributeMaxDynamicSharedMemorySize, GEMM_SMEM_BYTES);

    // 0) weight transpose + bf16 split
    k_wsplit<0><<<dim3(N1c / 32, K1c / 32, Hn), 256>>>(W_hid);
    k_wsplit<1><<<dim3(N2c / 32, K1c / 32, Hn), 256>>>(W_og);
    // 1) chunk sums + serial scan over chunks
    k_chunksum<<<Bsz * NC, 256>>>(heads_input);
    k_chunkscan<<<Bsz, 256>>>();
    // 2) fused exclusive csum + LN + build x (bf16 hi/lo)
    k_csumlnx<<<Bsz * NC, 256>>>(heads_input, g_csum, beta_csum);
    // 3) GEMM1 (split-bf16 mma.sync): per-head (16384 x 384 x 256)
    k_gemm_mma<N1c, 0><<<dim3(N1c / 128, Tsz / 128, Hn), 256, GEMM_SMEM_BYTES>>>(b_hid);
    // 4) fused LN stats + gates + chunk (F,I)
    k_gatescan<<<Bsz * NC, 256>>>(g_hid, beta_hid);
    // 5) inter-chunk scan
    k_scanB<<<Bsz, 256>>>(init_cx);
    // 6) recompute gates + scan cell + write cell (bf16 hi/lo)
    k_scanC<<<Bsz * NC, 256>>>(g_hid, beta_hid);
    // 7) GEMM2 (split-bf16 mma.sync): per-head (16384 x 128 x 256)
    k_gemm_mma<N2c, 1><<<dim3(N2c / 128, Tsz / 128, Hn), 256, GEMM_SMEM_BYTES>>>(b_og);
    // 8) final LN + sigmoid*cell
    k_out<<<Tsz, 256>>>(g_og, beta_og, out);
}

// round 15
// speedup vs baseline: 1.1494x; 1.0305x over previous
#include <cuda_runtime.h>
#include <cuda_bf16.h>
#include <math.h>
#include <cstdint>

// Problem constants
#define Bsz 4
#define Ssz 4096
#define Hn  8
#define DIc 128
#define DOc 128
#define Tsz (Bsz*Ssz)        // 16384 tokens
#define K1c 256              // 2*DI
#define N1c 384              // 3*DO
#define N2c 128
#define NC  128              // scan chunks
#define LC  (Ssz/NC)         // 32 steps per chunk
#define EPSf 1e-6f

// ---------------- static scratch (device globals; no allocation) -------------
__device__ __align__(16) __nv_bfloat16 buf_xh [(size_t)Tsz*Hn*K1c];  // A1 hi ([in, ln(csum)])
__device__ __align__(16) __nv_bfloat16 buf_xl [(size_t)Tsz*Hn*K1c];  // A1 lo
__device__ __align__(16) __nv_bfloat16 buf_cellh[(size_t)Tsz*Hn*DOc]; // cell hi
__device__ __align__(16) __nv_bfloat16 buf_celll[(size_t)Tsz*Hn*DOc]; // cell lo
__device__ float buf_h3  [(size_t)Tsz*Hn*N1c];
__device__ float buf_og  [(size_t)Tsz*Hn*DOc];
__device__ float buf_chunk[Bsz*NC*Hn*DIc];
__device__ float buf_Fc  [Bsz*NC*Hn*DOc];
__device__ float buf_Ic  [Bsz*NC*Hn*DOc];
__device__ int   flag1[Bsz*NC];
__device__ int   flag2[Bsz*NC];
// pre-split / transposed weights: [h][n][k] bf16 hi/lo
__device__ __align__(16) __nv_bfloat16 wt1_hi[(size_t)Hn*N1c*K1c];
__device__ __align__(16) __nv_bfloat16 wt1_lo[(size_t)Hn*N1c*K1c];
__device__ __align__(16) __nv_bfloat16 wt2_hi[(size_t)Hn*N2c*K1c];
__device__ __align__(16) __nv_bfloat16 wt2_lo[(size_t)Hn*N2c*K1c];

// ---------------- PTX helpers -------------------------------------------------
__device__ __forceinline__ uint32_t smem_u32(const void* p) {
    uint32_t a;
    asm("{ .reg .u64 t; cvta.to.shared.u64 t, %1; cvt.u32.u64 %0, t; }" : "=r"(a) : "l"(p));
    return a;
}
#define CPA16(sm_addr, gm_ptr) \
    asm volatile("cp.async.cg.shared.global [%0], [%1], 16;" \
                 :: "r"(sm_addr), "l"(gm_ptr) : "memory")
#define CPA_COMMIT asm volatile("cp.async.commit_group;" ::: "memory")
#define CPA_WAIT0  asm volatile("cp.async.wait_group 0;"  ::: "memory")

#define LDSM_X4(r0,r1,r2,r3,addr) \
    asm volatile("ldmatrix.sync.aligned.m8n8.x4.shared.b16 {%0,%1,%2,%3},[%4];" \
                 : "=r"(r0),"=r"(r1),"=r"(r2),"=r"(r3) : "r"(addr))

#define MMA16816(d, a, b) \
    asm volatile("mma.sync.aligned.m16n8k16.row.col.f32.bf16.bf16.f32 " \
                 "{%0,%1,%2,%3},{%4,%5,%6,%7},{%8,%9},{%0,%1,%2,%3};" \
                 : "+f"((d)[0]),"+f"((d)[1]),"+f"((d)[2]),"+f"((d)[3]) \
                 : "r"((a)[0]),"r"((a)[1]),"r"((a)[2]),"r"((a)[3]), \
                   "r"((b)[0]),"r"((b)[1]))

__device__ __forceinline__ void bsplit(float v, __nv_bfloat16& hi, __nv_bfloat16& lo) {
    hi = __float2bfloat16_rn(v);
    lo = __float2bfloat16_rn(v - __bfloat162float(hi));
}
__device__ __forceinline__ void bsplit4(float4 v, uint2& hi, uint2& lo) {
    __nv_bfloat16 h0,l0,h1,l1,h2,l2,h3,l3;
    bsplit(v.x,h0,l0); bsplit(v.y,h1,l1); bsplit(v.z,h2,l2); bsplit(v.w,h3,l3);
    hi.x = (uint32_t)__bfloat16_as_ushort(h0) | ((uint32_t)__bfloat16_as_ushort(h1) << 16);
    hi.y = (uint32_t)__bfloat16_as_ushort(h2) | ((uint32_t)__bfloat16_as_ushort(h3) << 16);
    lo.x = (uint32_t)__bfloat16_as_ushort(l0) | ((uint32_t)__bfloat16_as_ushort(l1) << 16);
    lo.y = (uint32_t)__bfloat16_as_ushort(l2) | ((uint32_t)__bfloat16_as_ushort(l3) << 16);
}
__device__ __forceinline__ float4 bunpack4(uint2 h, uint2 l) {
    float4 r;
    r.x = __bfloat162float(__ushort_as_bfloat16((unsigned short)(h.x & 0xffff)))
        + __bfloat162float(__ushort_as_bfloat16((unsigned short)(l.x & 0xffff)));
    r.y = __bfloat162float(__ushort_as_bfloat16((unsigned short)(h.x >> 16)))
        + __bfloat162float(__ushort_as_bfloat16((unsigned short)(l.x >> 16)));
    r.z = __bfloat162float(__ushort_as_bfloat16((unsigned short)(h.y & 0xffff)))
        + __bfloat162float(__ushort_as_bfloat16((unsigned short)(l.y & 0xffff)));
    r.w = __bfloat162float(__ushort_as_bfloat16((unsigned short)(h.y >> 16)))
        + __bfloat162float(__ushort_as_bfloat16((unsigned short)(l.y >> 16)));
    return r;
}
__device__ __forceinline__ float4 ld4(const float* p) { return *(const float4*)p; }
__device__ __forceinline__ void st4(float* p, float4 v) { *(float4*)p = v; }
__device__ __forceinline__ float4 ldcg4(const float* p) { return __ldcg((const float4*)p); }

// ---------------- helpers ----------------------------------------------------
// 1-sync block reduce (256 threads, double-buffered by bi = iteration parity)
__device__ __forceinline__ void block_reduce2_db(float& s, float& ss, int bi) {
    __shared__ float sh[2][2][8];
    #pragma unroll
    for (int o = 16; o > 0; o >>= 1) {
        s  += __shfl_down_sync(0xffffffffu, s,  o);
        ss += __shfl_down_sync(0xffffffffu, ss, o);
    }
    int lane = threadIdx.x & 31, w = threadIdx.x >> 5;
    if (lane == 0) { sh[bi][0][w] = s; sh[bi][1][w] = ss; }
    __syncthreads();
    float rs = 0.f, rss = 0.f;
    #pragma unroll
    for (int k = 0; k < 8; k++) { rs += sh[bi][0][k]; rss += sh[bi][1][k]; }
    s = rs; ss = rss;
}

__device__ __forceinline__ float sigm(float x) { return 1.f / (1.f + expf(-x)); }

// ---------------- K0: weight transpose + bf16 split (smem tiled) -------------
template <int WHICH>
__global__ void k_wsplit(const float* __restrict__ W) {
    const int N = (WHICH == 0) ? N1c : N2c;
    __nv_bfloat16* Whi = (WHICH == 0) ? wt1_hi : wt2_hi;
    __nv_bfloat16* Wlo = (WHICH == 0) ? wt1_lo : wt2_lo;
    __shared__ float tile[32][33];
    const int n0 = blockIdx.x * 32, k0 = blockIdx.y * 32, hh = blockIdx.z;
    const int tid = threadIdx.x;
    {
        int r = tid >> 3, cq = tid & 7;
        float4 v = ld4(W + ((size_t)hh * K1c + k0 + r) * N + n0 + cq * 4);
        tile[r][cq * 4 + 0] = v.x; tile[r][cq * 4 + 1] = v.y;
        tile[r][cq * 4 + 2] = v.z; tile[r][cq * 4 + 3] = v.w;
    }
    __syncthreads();
    {
        int nr = tid >> 3, kq = tid & 7;
        float4 v;
        v.x = tile[kq * 4 + 0][nr]; v.y = tile[kq * 4 + 1][nr];
        v.z = tile[kq * 4 + 2][nr]; v.w = tile[kq * 4 + 3][nr];
        uint2 hi, lo;
        bsplit4(v, hi, lo);
        size_t o = ((size_t)hh * N + n0 + nr) * K1c + k0 + kq * 4;
        *(uint2*)(Whi + o) = hi;
        *(uint2*)(Wlo + o) = lo;
    }
}

// ---------------- K1: single-pass cumsum + LN + assemble x (lookback) --------
__global__ void __launch_bounds__(256) k_scan1(const float* __restrict__ in,
        const float* __restrict__ gc, const float* __restrict__ bc) {
    int blk = blockIdx.x;                 // b*NC + c
    int b = blk / NC;
    int tid = threadIdx.x;
    int q4 = tid * 4;
    size_t t0 = (size_t)blk * LC;
    // phase1: chunk sum
    float4 s4 = make_float4(0.f, 0.f, 0.f, 0.f);
    #pragma unroll 4
    for (int i = 0; i < LC; i++) {
        float4 v = ld4(in + ((t0 + i) << 10) + q4);
        s4.x += v.x; s4.y += v.y; s4.z += v.z; s4.w += v.w;
    }
    st4(buf_chunk + ((size_t)blk << 10) + q4, s4);
    __threadfence();
    __syncthreads();
    if (tid == 0) atomicExch(&flag1[blk], 1);
    // lookback: wait for predecessors, then parallel-sum their aggregates
    int cs = b * NC;
    for (int j = cs + tid; j < blk; j += 256)
        while (((volatile const int*)flag1)[j] == 0) {}
    __threadfence();
    __syncthreads();
    float4 run = make_float4(0.f, 0.f, 0.f, 0.f);
    for (int j = cs; j < blk; j++) {
        float4 a = ldcg4(buf_chunk + ((size_t)j << 10) + q4);
        run.x += a.x; run.y += a.y; run.z += a.z; run.w += a.w;
    }
    // phase2: exclusive csum + LN + split writes (input re-read hits L2/L1)
    float4 g4 = ld4(gc + q4), b4 = ld4(bc + q4);
    int n = q4 >> 7, d = q4 & 127;
    float4 ip = ld4(in + (t0 << 10) + q4);
    for (int i = 0; i < LC; i++) {
        size_t t = t0 + i;
        float4 ipn;
        if (i + 1 < LC) ipn = ld4(in + ((t + 1) << 10) + q4);
        float s  = run.x + run.y + run.z + run.w;
        float ss = run.x * run.x + run.y * run.y + run.z * run.z + run.w * run.w;
        block_reduce2_db(s, ss, i & 1);
        float mu = s * (1.f / 1024.f);
        float var = ss * (1.f / 1024.f) - mu * mu;
        float rs = rsqrtf(var + EPSf);
        float4 ln;
        ln.x = (run.x - mu) * rs * g4.x + b4.x;
        ln.y = (run.y - mu) * rs * g4.y + b4.y;
        ln.z = (run.z - mu) * rs * g4.z + b4.z;
        ln.w = (run.w - mu) * rs * g4.w + b4.w;
        size_t xb = (t << 11) + n * K1c + d;
        uint2 hi, lo;
        bsplit4(ip, hi, lo);
        *(uint2*)(buf_xh + xb) = hi; *(uint2*)(buf_xl + xb) = lo;
        bsplit4(ln, hi, lo);
        *(uint2*)(buf_xh + xb + 128) = hi; *(uint2*)(buf_xl + xb + 128) = lo;
        run.x += ip.x; run.y += ip.y; run.z += ip.z; run.w += ip.w;
        ip = ipn;
    }
}

// ---------------- split-bf16 mma.sync GEMM -----------------------------------
#define STG_BUF   10240                // 128 rows x 80B
#define STG_BYTES (4 * STG_BUF)
#define GEMM_SMEM_BYTES (2 * STG_BYTES)

template <int NTOT, int WHICH>
__global__ void __launch_bounds__(256, 2) k_gemm_mma(const float* __restrict__ bias) {
    const __nv_bfloat16* Bh = WHICH ? wt2_hi  : wt1_hi;
    const __nv_bfloat16* Bl = WHICH ? wt2_lo  : wt1_lo;
    float* Y = WHICH ? buf_og : buf_h3;

    extern __shared__ char smch[];
    const uint32_t sbase = smem_u32(smch);

    const int tid = threadIdx.x;
    const int h  = blockIdx.z;
    const int m0 = blockIdx.y * 128;
    const int n0 = blockIdx.x * 128;
    const int w = tid >> 5, lane = tid & 31;
    const int wm = w & 3, wn = w >> 2;

    float acc[2][8][4];
    #pragma unroll
    for (int i = 0; i < 2; i++)
        #pragma unroll
        for (int j = 0; j < 8; j++)
            #pragma unroll
            for (int q = 0; q < 4; q++) acc[i][j][q] = 0.f;

    auto stage = [&](int kt, int st) {
        const uint32_t sb = sbase + st * STG_BYTES;
        const int kb = kt * 32;
        #pragma unroll
        for (int g = 0; g < 2; g++) {
            int idx = tid + 256 * g;
            int row = idx >> 2, c = idx & 3;
            uint32_t soff = (uint32_t)(row * 80 + c * 16);
            const __nv_bfloat16 *pAh, *pAl;
            if (WHICH == 1 && kb >= 128) {
                size_t ga = ((size_t)(m0 + row) * Hn + h) * DOc + (kb - 128) + c * 8;
                pAh = buf_cellh + ga; pAl = buf_celll + ga;
            } else {
                size_t ga = ((size_t)(m0 + row) * Hn + h) * K1c + kb + c * 8;
                pAh = buf_xh + ga; pAl = buf_xl + ga;
            }
            CPA16(sb + soff,               pAh);
            CPA16(sb + STG_BUF + soff,     pAl);
            size_t gb = ((size_t)h * NTOT + n0 + row) * K1c + kb + c * 8;
            CPA16(sb + 2 * STG_BUF + soff, Bh + gb);
            CPA16(sb + 3 * STG_BUF + soff, Bl + gb);
        }
    };

    const int lrow = lane & 15;
    const int lhv  = lane >> 4;

    stage(0, 0);
    CPA_COMMIT;

    for (int kt = 0; kt < 8; kt++) {
        const int st = kt & 1;
        const uint32_t sb = sbase + st * STG_BYTES;
        CPA_WAIT0;
        __syncthreads();
        if (kt < 7) { stage(kt + 1, st ^ 1); CPA_COMMIT; }

        #pragma unroll
        for (int s = 0; s < 2; s++) {
            const int ch = s * 2 + lhv;
            uint32_t ah[2][4], al[2][4];
            #pragma unroll
            for (int im = 0; im < 2; im++) {
                int row = wm * 32 + im * 16 + lrow;
                uint32_t ad = sb + (uint32_t)(row * 80 + (ch << 4));
                LDSM_X4(ah[im][0], ah[im][1], ah[im][2], ah[im][3], ad);
                LDSM_X4(al[im][0], al[im][1], al[im][2], al[im][3], ad + STG_BUF);
            }
            uint32_t bh[8][2], bl[8][2];
            #pragma unroll
            for (int jn = 0; jn < 4; jn++) {
                int row = wn * 64 + jn * 16 + lrow;
                uint32_t ad = sb + 2 * STG_BUF + (uint32_t)(row * 80 + (ch << 4));
                uint32_t r0, r1, r2, r3;
                LDSM_X4(r0, r1, r2, r3, ad);
                bh[2 * jn][0] = r0; bh[2 * jn][1] = r2;
                bh[2 * jn + 1][0] = r1; bh[2 * jn + 1][1] = r3;
                LDSM_X4(r0, r1, r2, r3, ad + STG_BUF);
                bl[2 * jn][0] = r0; bl[2 * jn][1] = r2;
                bl[2 * jn + 1][0] = r1; bl[2 * jn + 1][1] = r3;
            }
            #pragma unroll
            for (int im = 0; im < 2; im++)
                #pragma unroll
                for (int jn = 0; jn < 8; jn++) {
                    MMA16816(acc[im][jn], ah[im], bh[jn]);
                    MMA16816(acc[im][jn], ah[im], bl[jn]);
                    MMA16816(acc[im][jn], al[im], bh[jn]);
                }
        }
        __syncthreads();
    }

    const int gr = lane >> 2, gc = (lane & 3) * 2;
    #pragma unroll
    for (int im = 0; im < 2; im++) {
        #pragma unroll
        for (int jn = 0; jn < 8; jn++) {
            int row = m0 + wm * 32 + im * 16 + gr;
            int col = n0 + wn * 64 + jn * 8 + gc;
            float2 bb = *(const float2*)(bias + h * NTOT + col);
            float* y0 = Y + ((size_t)row * Hn + h) * NTOT + col;
            y0[0] = acc[im][jn][0] + bb.x;
            y0[1] = acc[im][jn][1] + bb.y;
            float* y1 = Y + ((size_t)(row + 8) * Hn + h) * NTOT + col;
            y1[0] = acc[im][jn][2] + bb.x;
            y1[1] = acc[im][jn][3] + bb.y;
        }
    }
}

// ---------------- K2: single-pass gates + cell scan (lookback) ---------------
__global__ void __launch_bounds__(256) k_scan2(const float* __restrict__ gh,
        const float* __restrict__ bh, const float* __restrict__ init_cx) {
    __shared__ float2 stats_s[LC];
    int blk = blockIdx.x;
    int b = blk / NC;
    int tid = threadIdx.x, q4 = tid * 4;
    int n = tid >> 5, d = (tid & 31) * 4;
    size_t t0 = (size_t)blk * LC;
    float4 gv[3], bv[3];
    #pragma unroll
    for (int g = 0; g < 3; g++) {
        gv[g] = ld4(gh + (n * 3 + g) * 128 + d);
        bv[g] = ld4(bh + (n * 3 + g) * 128 + d);
    }
    // phase1: LN stats (to smem) + gates + chunk (F, I)
    float4 F = make_float4(1.f, 1.f, 1.f, 1.f);
    float4 I = make_float4(0.f, 0.f, 0.f, 0.f);
    const float* hp0 = buf_h3 + t0 * (Hn * N1c) + n * N1c + d;
    float4 xi = ld4(hp0), xf = ld4(hp0 + 128), xv = ld4(hp0 + 256);
    for (int i = 0; i < LC; i++) {
        size_t t = t0 + i;
        float4 xin, xfn, xvn;
        if (i + 1 < LC) {
            const float* hp = buf_h3 + (t + 1) * (Hn * N1c) + n * N1c + d;
            xin = ld4(hp); xfn = ld4(hp + 128); xvn = ld4(hp + 256);
        }
        float s  = xi.x + xi.y + xi.z + xi.w + xf.x + xf.y + xf.z + xf.w
                 + xv.x + xv.y + xv.z + xv.w;
        float ss = xi.x*xi.x + xi.y*xi.y + xi.z*xi.z + xi.w*xi.w
                 + xf.x*xf.x + xf.y*xf.y + xf.z*xf.z + xf.w*xf.w
                 + xv.x*xv.x + xv.y*xv.y + xv.z*xv.z + xv.w*xv.w;
        block_reduce2_db(s, ss, i & 1);
        float mu  = s * (1.f / 3072.f);
        float var = ss * (1.f / 3072.f) - mu * mu;
        float rs  = rsqrtf(var + EPSf);
        if (tid == 0) stats_s[i] = make_float2(mu, rs);
        float4 fg, ih;
        fg.x = sigm((xf.x - mu) * rs * gv[1].x + bv[1].x);
        fg.y = sigm((xf.y - mu) * rs * gv[1].y + bv[1].y);
        fg.z = sigm((xf.z - mu) * rs * gv[1].z + bv[1].z);
        fg.w = sigm((xf.w - mu) * rs * gv[1].w + bv[1].w);
        ih.x = sigm((xi.x - mu) * rs * gv[0].x + bv[0].x) * fmaxf((xv.x - mu) * rs * gv[2].x + bv[2].x, 0.f);
        ih.y = sigm((xi.y - mu) * rs * gv[0].y + bv[0].y) * fmaxf((xv.y - mu) * rs * gv[2].y + bv[2].y, 0.f);
        ih.z = sigm((xi.z - mu) * rs * gv[0].z + bv[0].z) * fmaxf((xv.z - mu) * rs * gv[2].z + bv[2].z, 0.f);
        ih.w = sigm((xi.w - mu) * rs * gv[0].w + bv[0].w) * fmaxf((xv.w - mu) * rs * gv[2].w + bv[2].w, 0.f);
        F.x *= fg.x; F.y *= fg.y; F.z *= fg.z; F.w *= fg.w;
        I.x = fg.x * I.x + ih.x; I.y = fg.y * I.y + ih.y;
        I.z = fg.z * I.z + ih.z; I.w = fg.w * I.w + ih.w;
        xi = xin; xf = xfn; xv = xvn;
    }
    st4(buf_Fc + ((size_t)blk << 10) + q4, F);
    st4(buf_Ic + ((size_t)blk << 10) + q4, I);
    __threadfence();
    __syncthreads();
    if (tid == 0) atomicExch(&flag2[blk], 1);
    // lookback: compose predecessor transforms in chunk order
    int cs = b * NC;
    for (int j = cs + tid; j < blk; j += 256)
        while (((volatile const int*)flag2)[j] == 0) {}
    __threadfence();
    __syncthreads();
    float4 PF = make_float4(1.f, 1.f, 1.f, 1.f);
    float4 PI = make_float4(0.f, 0.f, 0.f, 0.f);
    for (int j = cs; j < blk; j++) {
        float4 Fj = ldcg4(buf_Fc + ((size_t)j << 10) + q4);
        float4 Ij = ldcg4(buf_Ic + ((size_t)j << 10) + q4);
        PF.x = Fj.x * PF.x; PI.x = Fj.x * PI.x + Ij.x;
        PF.y = Fj.y * PF.y; PI.y = Fj.y * PI.y + Ij.y;
        PF.z = Fj.z * PF.z; PI.z = Fj.z * PI.z + Ij.z;
        PF.w = Fj.w * PF.w; PI.w = Fj.w * PI.w + Ij.w;
    }
    float4 ini = ld4(init_cx + q4);
    float4 cc;
    cc.x = PF.x * ini.x + PI.x; cc.y = PF.y * ini.y + PI.y;
    cc.z = PF.z * ini.z + PI.z; cc.w = PF.w * ini.w + PI.w;
    // phase2: recompute gates (h3 re-read, mostly L2) + scan cell + write split
    const float* hq0 = buf_h3 + t0 * (Hn * N1c) + n * N1c + d;
    xi = ld4(hq0); xf = ld4(hq0 + 128); xv = ld4(hq0 + 256);
    for (int i = 0; i < LC; i++) {
        size_t t = t0 + i;
        float4 xin, xfn, xvn;
        if (i + 1 < LC) {
            const float* hp = buf_h3 + (t + 1) * (Hn * N1c) + n * N1c + d;
            xin = ld4(hp); xfn = ld4(hp + 128); xvn = ld4(hp + 256);
        }
        float2 st2 = stats_s[i];
        float mu = st2.x, rs = st2.y;
        float4 fg, ih;
        fg.x = sigm((xf.x - mu) * rs * gv[1].x + bv[1].x);
        fg.y = sigm((xf.y - mu) * rs * gv[1].y + bv[1].y);
        fg.z = sigm((xf.z - mu) * rs * gv[1].z + bv[1].z);
        fg.w = sigm((xf.w - mu) * rs * gv[1].w + bv[1].w);
        ih.x = sigm((xi.x - mu) * rs * gv[0].x + bv[0].x) * fmaxf((xv.x - mu) * rs * gv[2].x + bv[2].x, 0.f);
        ih.y = sigm((xi.y - mu) * rs * gv[0].y + bv[0].y) * fmaxf((xv.y - mu) * rs * gv[2].y + bv[2].y, 0.f);
        ih.z = sigm((xi.z - mu) * rs * gv[0].z + bv[0].z) * fmaxf((xv.z - mu) * rs * gv[2].z + bv[2].z, 0.f);
        ih.w = sigm((xi.w - mu) * rs * gv[0].w + bv[0].w) * fmaxf((xv.w - mu) * rs * gv[2].w + bv[2].w, 0.f);
        cc.x = fg.x * cc.x + ih.x; cc.y = fg.y * cc.y + ih.y;
        cc.z = fg.z * cc.z + ih.z; cc.w = fg.w * cc.w + ih.w;
        uint2 hi, lo;
        bsplit4(cc, hi, lo);
        *(uint2*)(buf_cellh + (t << 10) + q4) = hi;
        *(uint2*)(buf_celll + (t << 10) + q4) = lo;
        xi = xin; xf = xfn; xv = xvn;
    }
}

// ---------------- K7: token LN of og (1024) + sigmoid * cell -----------------
__global__ void __launch_bounds__(256) k_out(const float* __restrict__ gg,
        const float* __restrict__ bg, float* __restrict__ out) {
    int t = blockIdx.x;
    int i = threadIdx.x * 4;
    float4 o4 = ld4(buf_og + ((size_t)t << 10) + i);
    float s  = o4.x + o4.y + o4.z + o4.w;
    float ss = o4.x * o4.x + o4.y * o4.y + o4.z * o4.z + o4.w * o4.w;
    block_reduce2_db(s, ss, 0);
    float mu  = s * (1.f / 1024.f);
    float var = ss * (1.f / 1024.f) - mu * mu;
    float rs  = rsqrtf(var + EPSf);
    float4 g4 = ld4(gg + i), b4 = ld4(bg + i);
    float4 cell = bunpack4(*(const uint2*)(buf_cellh + ((size_t)t << 10) + i),
                           *(const uint2*)(buf_celll + ((size_t)t << 10) + i));
    float4 r;
    r.x = cell.x * sigm((o4.x - mu) * rs * g4.x + b4.x);
    r.y = cell.y * sigm((o4.y - mu) * rs * g4.y + b4.y);
    r.z = cell.z * sigm((o4.z - mu) * rs * g4.z + b4.z);
    r.w = cell.w * sigm((o4.w - mu) * rs * g4.w + b4.w);
    st4(out + ((size_t)t << 10) + i, r);
}

// ---------------- launch ------------------------------------------------------
extern "C" void kernel_launch(void* const* d_in, const int* in_sizes, int n_in,
                              void* d_out, int out_size) {
    const float* heads_input = (const float*)d_in[0];
    const float* W_hid       = (const float*)d_in[1];
    const float* b_hid       = (const float*)d_in[2];
    const float* g_csum      = (const float*)d_in[3];
    const float* beta_csum   = (const float*)d_in[4];
    const float* g_hid       = (const float*)d_in[5];
    const float* beta_hid    = (const float*)d_in[6];
    const float* W_og        = (const float*)d_in[7];
    const float* b_og        = (const float*)d_in[8];
    const float* g_og        = (const float*)d_in[9];
    const float* beta_og     = (const float*)d_in[10];
    const float* init_cx     = (const float*)d_in[11];
    float* out = (float*)d_out;

    cudaFuncSetAttribute(k_gemm_mma<N1c, 0>,
        cudaFuncAttributeMaxDynamicSharedMemorySize, GEMM_SMEM_BYTES);
    cudaFuncSetAttribute(k_gemm_mma<N2c, 1>,
        cudaFuncAttributeMaxDynamicSharedMemorySize, GEMM_SMEM_BYTES);

    // reset lookback flags (graph-capturable memset nodes)
    void *pf1 = nullptr, *pf2 = nullptr;
    cudaGetSymbolAddress(&pf1, flag1);
    cudaGetSymbolAddress(&pf2, flag2);
    cudaMemsetAsync(pf1, 0, sizeof(int) * Bsz * NC);
    cudaMemsetAsync(pf2, 0, sizeof(int) * Bsz * NC);

    // 0) weight transpose + bf16 split
    k_wsplit<0><<<dim3(N1c / 32, K1c / 32, Hn), 256>>>(W_hid);
    k_wsplit<1><<<dim3(N2c / 32, K1c / 32, Hn), 256>>>(W_og);
    // 1) single-pass cumsum + LN + build x (decoupled lookback)
    k_scan1<<<Bsz * NC, 256>>>(heads_input, g_csum, beta_csum);
    // 2) GEMM1 (split-bf16 mma.sync): per-head (16384 x 384 x 256)
    k_gemm_mma<N1c, 0><<<dim3(N1c / 128, Tsz / 128, Hn), 256, GEMM_SMEM_BYTES>>>(b_hid);
    // 3) single-pass gates + cell scan (decoupled lookback)
    k_scan2<<<Bsz * NC, 256>>>(g_hid, beta_hid, init_cx);
    // 4) GEMM2 (split-bf16 mma.sync): per-head (16384 x 128 x 256)
    k_gemm_mma<N2c, 1><<<dim3(N2c / 128, Tsz / 128, Hn), 256, GEMM_SMEM_BYTES>>>(b_og);
    // 5) final LN + sigmoid*cell
    k_out<<<Tsz, 256>>>(g_og, beta_og, out);
}